// round 16
// baseline (speedup 1.0000x reference)
#include <cuda_runtime.h>
#include <cuda_bf16.h>
#include <cuda_fp16.h>
#include <mma.h>

using namespace nvcuda;

// Problem sizes (fixed by the reference: B=4, L=512, D=256)
#define B 4
#define L 512
#define D 256
#define D2 (D/2)              // 128 half2 pairs
#define R_SIZE (B*L*D)        // 524288 floats (r)
#define A_SIZE (B*L*L)        // 1048576 floats (alpha)

#define TILE 64               // i/j tile for scores kernel
#define NT   (L/TILE)         // 8 tiles per dim
#define NPAIR (NT*(NT+1)/2)   // 36 upper-tri tile pairs per batch
#define SH2  130              // half2 row stride (proven conflict-free layout)
#define SCORES_GRID (B*NPAIR) // 144

// Scratch: fp32 pre-softmax scores; fp16 H for the tensor-core GEMM
__device__ float  g_scores[B*L*L];
__device__ __half g_H_h[R_SIZE];

__device__ __forceinline__ __half2 tanh2_approx(__half2 x) {
    unsigned xin = *reinterpret_cast<unsigned*>(&x);
    unsigned yout;
    asm("tanh.approx.f16x2 %0, %1;" : "=r"(yout) : "r"(xin));
    return *reinterpret_cast<__half2*>(&yout);
}

// ---------------------------------------------------------------------------
// Kernel 1 (round-6 proven, 39us = MUFU wall): scores[b,i,j] =
// sum_d tanh(H[b,i,d]+H[b,j,d])*w[d]  (bias dropped: softmax shift-invariant)
// Upper-tri 64x64 tiles, mirrored. Plus free H->fp16 copy.
// ---------------------------------------------------------------------------
__global__ void __launch_bounds__(512)
scores_kernel(const float* __restrict__ H,
              const float* __restrict__ w) {
    extern __shared__ __align__(16) unsigned smraw[];
    __half2* sHi = reinterpret_cast<__half2*>(smraw);           // 64 * SH2
    __half2* sHj = sHi + 64 * SH2;                              // 64 * SH2
    __half2* sWh = sHj + 64 * SH2;                              // D2

    const int blk = blockIdx.x;
    const int b   = blk / NPAIR;
    int p = blk % NPAIR;
    int ti = 0, rowlen = NT;
    while (p >= rowlen) { p -= rowlen; ++ti; --rowlen; }
    const int tj = ti + p;
    const int i0 = ti * TILE;
    const int j0 = tj * TILE;

    const int tid = threadIdx.x;
    const float* Hb = H + (size_t)b * L * D;

    if (tid < D2) {
        float2 wv = reinterpret_cast<const float2*>(w)[tid];
        sWh[tid] = __float22half2_rn(wv);
    }

    // H -> fp16 copy (grid-stride; ~2 float4 per thread, hidden under MUFU)
    for (int idx = blk * 512 + tid; idx < R_SIZE / 4; idx += SCORES_GRID * 512) {
        float4 v = *reinterpret_cast<const float4*>(H + 4 * idx);
        __half2* dst = reinterpret_cast<__half2*>(g_H_h + 4 * idx);
        dst[0] = __floats2half2_rn(v.x, v.y);
        dst[1] = __floats2half2_rn(v.z, v.w);
    }

    #pragma unroll
    for (int it = 0; it < 8; ++it) {
        int e = tid + 512 * it;
        int row = e >> 6;
        int c4  = e & 63;
        float4 v = *reinterpret_cast<const float4*>(Hb + (size_t)(i0 + row) * D + 4 * c4);
        sHi[row * SH2 + 2 * c4]     = __floats2half2_rn(v.x, v.y);
        sHi[row * SH2 + 2 * c4 + 1] = __floats2half2_rn(v.z, v.w);
    }
    #pragma unroll
    for (int it = 0; it < 8; ++it) {
        int e = tid + 512 * it;
        int row = e >> 6;
        int c4  = e & 63;
        float4 v = *reinterpret_cast<const float4*>(Hb + (size_t)(j0 + row) * D + 4 * c4);
        sHj[row * SH2 + 2 * c4]     = __floats2half2_rn(v.x, v.y);
        sHj[row * SH2 + 2 * c4 + 1] = __floats2half2_rn(v.z, v.w);
    }
    __syncthreads();

    const int tx = tid & 15;
    const int ty = tid >> 4;

    float accf[2][4];
    #pragma unroll
    for (int m = 0; m < 2; ++m)
        #pragma unroll
        for (int n = 0; n < 4; ++n) accf[m][n] = 0.0f;

    #pragma unroll 2
    for (int c = 0; c < D2 / 4; ++c) {
        __half2 acc2[2][4];
        #pragma unroll
        for (int m = 0; m < 2; ++m)
            #pragma unroll
            for (int n = 0; n < 4; ++n)
                acc2[m][n] = __halves2half2(__ushort_as_half(0), __ushort_as_half(0));

        #pragma unroll
        for (int u = 0; u < 4; ++u) {
            const int dp = 4 * c + u;
            const __half2 w2 = sWh[dp];
            __half2 hi[2], hj[4];
            #pragma unroll
            for (int m = 0; m < 2; ++m) hi[m] = sHi[(ty + 32 * m) * SH2 + dp];
            #pragma unroll
            for (int n = 0; n < 4; ++n) hj[n] = sHj[(tx + 16 * n) * SH2 + dp];
            #pragma unroll
            for (int m = 0; m < 2; ++m)
                #pragma unroll
                for (int n = 0; n < 4; ++n) {
                    __half2 t = tanh2_approx(__hadd2(hi[m], hj[n]));
                    acc2[m][n] = __hfma2(t, w2, acc2[m][n]);
                }
        }

        #pragma unroll
        for (int m = 0; m < 2; ++m)
            #pragma unroll
            for (int n = 0; n < 4; ++n) {
                float2 f = __half22float2(acc2[m][n]);
                accf[m][n] += f.x + f.y;
            }
    }

    const int mirror = (ti != tj);
    #pragma unroll
    for (int m = 0; m < 2; ++m) {
        int gi = i0 + ty + 32 * m;
        #pragma unroll
        for (int n = 0; n < 4; ++n) {
            int gj = j0 + tx + 16 * n;
            float v = accf[m][n];
            g_scores[((size_t)b * L + gi) * L + gj] = v;
            if (mirror)
                g_scores[((size_t)b * L + gj) * L + gi] = v;
        }
    }
}

// ---------------------------------------------------------------------------
// Kernel 2: FUSED softmax + tensor-core GEMM.
// CTA: 64 i-rows x 128 d-cols; grid (2, 8, 4) = 64 CTAs, 256 thr (8 warps).
// Phase A: warp-per-row softmax (8 rows/warp) over scores read from L2;
//          normalized fp16 alpha written DIRECTLY into the smem A-tile
//          (1/sum folded in); bx==0 CTAs also write fp32 alpha to d_out.
// Phase B: round-15 proven wmma loop: 8 k-tiles of 64, H double-buffered,
//          warp (wy,wx) owns a 16x64 slab = 4 m16n16k16 fp32 fragments.
// ---------------------------------------------------------------------------
#define SLD 520   // alpha smem row stride (halves)
#define HLD 136   // H smem row stride (halves)
#define HTILE (64 * HLD)

__global__ void __launch_bounds__(256)
fused_softmax_wmma(float* __restrict__ out_alpha,
                   float* __restrict__ out_r) {
    extern __shared__ __align__(16) __half wsm[];
    __half* Sa = wsm;              // 64 * SLD  (normalized fp16 alpha)
    __half* Bs = wsm + 64 * SLD;   // 2 * HTILE (H tiles, double-buffered)

    const int bx  = blockIdx.x;            // d-block: 0 or 1
    const int d0  = bx * 128;
    const int it0 = blockIdx.y * 64;
    const int b   = blockIdx.z;

    const __half* Hm = g_H_h + (size_t)b * L * D + d0;            // 512 x 128
    float*        C  = out_r + ((size_t)b * L + it0) * D + d0;

    const int tid  = threadIdx.x;
    const int warp = tid >> 5;
    const int lane = tid & 31;

    // ---- Phase A: softmax, 8 rows per warp -------------------------------
    #pragma unroll 1
    for (int rr = 0; rr < 8; ++rr) {
        const int row = warp * 8 + rr;          // 0..63
        const size_t gbase = ((size_t)b * L + it0 + row) * L;
        const float4* S4 = reinterpret_cast<const float4*>(g_scores + gbase);

        float4 v[4];
        #pragma unroll
        for (int k = 0; k < 4; ++k) v[k] = S4[lane + 32 * k];

        float mx = -1e30f;
        #pragma unroll
        for (int k = 0; k < 4; ++k)
            mx = fmaxf(mx, fmaxf(fmaxf(v[k].x, v[k].y), fmaxf(v[k].z, v[k].w)));
        #pragma unroll
        for (int o = 16; o; o >>= 1) mx = fmaxf(mx, __shfl_xor_sync(0xffffffffu, mx, o));

        float s = 0.0f;
        #pragma unroll
        for (int k = 0; k < 4; ++k) {
            v[k].x = __expf(v[k].x - mx); v[k].y = __expf(v[k].y - mx);
            v[k].z = __expf(v[k].z - mx); v[k].w = __expf(v[k].w - mx);
            s += (v[k].x + v[k].y) + (v[k].z + v[k].w);
        }
        #pragma unroll
        for (int o = 16; o; o >>= 1) s += __shfl_xor_sync(0xffffffffu, s, o);
        const float inv = 1.0f / s;

        __half2* dst = reinterpret_cast<__half2*>(Sa + row * SLD);
        #pragma unroll
        for (int k = 0; k < 4; ++k) {
            float4 o4 = make_float4(v[k].x * inv, v[k].y * inv,
                                    v[k].z * inv, v[k].w * inv);
            dst[2 * (lane + 32 * k)]     = __floats2half2_rn(o4.x, o4.y);
            dst[2 * (lane + 32 * k) + 1] = __floats2half2_rn(o4.z, o4.w);
            if (bx == 0)
                *reinterpret_cast<float4*>(out_alpha + gbase + 4 * (lane + 32 * k)) = o4;
        }
    }

    // H k-tile 0 staging (before the sync; overlaps Phase A stragglers)
    #pragma unroll
    for (int t = 0; t < 4; ++t) {                 // 1024 float4
        int e = tid + 256 * t;
        int row = e >> 4, c4 = e & 15;
        float4 v = *reinterpret_cast<const float4*>(Hm + (size_t)row * D + 8 * c4);
        *reinterpret_cast<float4*>(Bs + row * HLD + 8 * c4) = v;
    }
    __syncthreads();

    // ---- Phase B: wmma GEMM  r[64x128] = alpha(64x512) @ H(512x128) ------
    const int wy = warp >> 1;    // 0..3: i-subtile (16 rows)
    const int wx = warp & 1;     // 0..1: d-subtile (64 cols)

    wmma::fragment<wmma::accumulator, 16, 16, 16, float> acc[4];
    #pragma unroll
    for (int n = 0; n < 4; ++n) wmma::fill_fragment(acc[n], 0.0f);

    #pragma unroll 1
    for (int kt = 0; kt < 8; ++kt) {
        const int cur = kt & 1, nxt = cur ^ 1;

        float4 pb[4];
        if (kt < 7) {
            const int k0n = (kt + 1) * 64;
            #pragma unroll
            for (int t = 0; t < 4; ++t) {
                int e = tid + 256 * t;
                int row = e >> 4, c4 = e & 15;
                pb[t] = *reinterpret_cast<const float4*>(Hm + (size_t)(k0n + row) * D + 8 * c4);
            }
        }

        const __half* Ac = Sa + kt * 64;          // column offset in alpha
        const __half* Bc = Bs + cur * HTILE;
        #pragma unroll
        for (int ks = 0; ks < 4; ++ks) {
            wmma::fragment<wmma::matrix_a, 16, 16, 16, __half, wmma::row_major> af;
            wmma::load_matrix_sync(af, Ac + (wy * 16) * SLD + ks * 16, SLD);
            #pragma unroll
            for (int n = 0; n < 4; ++n) {
                wmma::fragment<wmma::matrix_b, 16, 16, 16, __half, wmma::row_major> bf;
                wmma::load_matrix_sync(bf, Bc + (ks * 16) * HLD + wx * 64 + n * 16, HLD);
                wmma::mma_sync(acc[n], af, bf, acc[n]);
            }
        }

        if (kt < 7) {
            __half* Bn = Bs + nxt * HTILE;
            #pragma unroll
            for (int t = 0; t < 4; ++t) {
                int e = tid + 256 * t;
                int row = e >> 4, c4 = e & 15;
                *reinterpret_cast<float4*>(Bn + row * HLD + 8 * c4) = pb[t];
            }
        }
        __syncthreads();
    }

    #pragma unroll
    for (int n = 0; n < 4; ++n)
        wmma::store_matrix_sync(C + (size_t)(wy * 16) * D + wx * 64 + n * 16,
                                acc[n], D, wmma::mem_row_major);
}

// ---------------------------------------------------------------------------
extern "C" void kernel_launch(void* const* d_in, const int* in_sizes, int n_in,
                              void* d_out, int out_size) {
    const float* H = (const float*)d_in[0];
    const float* w = (const float*)d_in[1];

    float* out   = (float*)d_out;
    float* r     = out;            // first R_SIZE floats
    float* alpha = out + R_SIZE;   // next A_SIZE floats

    const int smem1 = (2 * 64 * SH2 + D2) * (int)sizeof(__half2);
    cudaFuncSetAttribute(scores_kernel,
                         cudaFuncAttributeMaxDynamicSharedMemorySize, smem1);

    const int smem2 = (64 * SLD + 2 * HTILE) * (int)sizeof(__half);
    cudaFuncSetAttribute(fused_softmax_wmma,
                         cudaFuncAttributeMaxDynamicSharedMemorySize, smem2);

    scores_kernel<<<SCORES_GRID, 512, smem1>>>(H, w);
    fused_softmax_wmma<<<dim3(2, 8, 4), 256, smem2>>>(alpha, r);
}

// round 17
// speedup vs baseline: 1.4994x; 1.4994x over previous
#include <cuda_runtime.h>
#include <cuda_bf16.h>
#include <cuda_fp16.h>
#include <mma.h>

using namespace nvcuda;

// Problem sizes (fixed by the reference: B=4, L=512, D=256)
#define B 4
#define L 512
#define D 256
#define D2 (D/2)              // 128 half2 pairs
#define R_SIZE (B*L*D)        // 524288 floats (r)
#define A_SIZE (B*L*L)        // 1048576 floats (alpha)

#define TILE 64               // i/j tile for scores kernel
#define NT   (L/TILE)         // 8 tiles per dim
#define NPAIR (NT*(NT+1)/2)   // 36 upper-tri tile pairs per batch
#define SH2  130              // half2 row stride (proven conflict-free)
#define SCORES_GRID (B*NPAIR) // 144

// Hybrid split: dims [0, DMU) on MUFU f16x2 path; dims [DMU, D) on the
// exp-identity fp32 FMA path.  DMU = 208 -> 104 half2 pairs (26 chunks of 4).
#define DMU   208
#define NID   (D - DMU)       // 48 identity dims
#define ELD   49              // fp32 exp-tile row stride (odd -> conflict-free)

// Scratch: fp32 pre-softmax scores; fp16 H for the tensor-core GEMM
__device__ float  g_scores[B*L*L];
__device__ __half g_H_h[R_SIZE];

__device__ __forceinline__ __half2 tanh2_approx(__half2 x) {
    unsigned xin = *reinterpret_cast<unsigned*>(&x);
    unsigned yout;
    asm("tanh.approx.f16x2 %0, %1;" : "=r"(yout) : "r"(xin));
    return *reinterpret_cast<__half2*>(&yout);
}

// Fast reciprocal: magic-constant init (ALU pipe) + 2 Newton steps (FMA pipe).
// rel err ~2e-4 after 2 steps; no MUFU.
__device__ __forceinline__ float frcp2(float x) {
    float y = __uint_as_float(0x7EF311C3u - __float_as_uint(x));
    y = y * fmaf(-x, y, 2.0f);
    y = y * fmaf(-x, y, 2.0f);
    return y;
}

// ---------------------------------------------------------------------------
// Kernel 1: scores[b,i,j] = sum_d tanh(H[b,i,d]+H[b,j,d])*w[d]
// (bias dropped: softmax shift-invariant). Upper-tri 64x64 tiles, mirrored.
// HYBRID: 208 dims on MUFU (round-6 proven loop) + 48 dims via the exact
// identity tanh(a+b) = (E-1)/(E+1), E = e^{2a}e^{2b}, on the fp32 FMA pipe
// (exp(2h) precomputed per row/dim during tile load).
// Plus the free H->fp16 copy for the wmma GEMM.
// ---------------------------------------------------------------------------
__global__ void __launch_bounds__(512)
scores_kernel(const float* __restrict__ H,
              const float* __restrict__ w) {
    extern __shared__ __align__(16) unsigned smraw[];
    __half2* sHi = reinterpret_cast<__half2*>(smraw);           // 64 * SH2
    __half2* sHj = sHi + 64 * SH2;                              // 64 * SH2
    __half2* sWh = sHj + 64 * SH2;                              // D2
    float*   sEi = reinterpret_cast<float*>(sWh + D2);          // 64 * ELD
    float*   sEj = sEi + 64 * ELD;                              // 64 * ELD
    float*   sWf = sEj + 64 * ELD;                              // NID

    const int blk = blockIdx.x;
    const int b   = blk / NPAIR;
    int p = blk % NPAIR;
    int ti = 0, rowlen = NT;
    while (p >= rowlen) { p -= rowlen; ++ti; --rowlen; }
    const int tj = ti + p;
    const int i0 = ti * TILE;
    const int j0 = tj * TILE;

    const int tid = threadIdx.x;
    const float* Hb = H + (size_t)b * L * D;

    if (tid < D2) {
        float2 wv = reinterpret_cast<const float2*>(w)[tid];
        sWh[tid] = __float22half2_rn(wv);
    }
    if (tid < NID) sWf[tid] = w[DMU + tid];

    // H -> fp16 copy (grid-stride; hidden under MUFU)
    for (int idx = blk * 512 + tid; idx < R_SIZE / 4; idx += SCORES_GRID * 512) {
        float4 v = *reinterpret_cast<const float4*>(H + 4 * idx);
        __half2* dst = reinterpret_cast<__half2*>(g_H_h + 4 * idx);
        dst[0] = __floats2half2_rn(v.x, v.y);
        dst[1] = __floats2half2_rn(v.z, v.w);
    }

    // f16 tiles (full D, pairs >= 104 unused by the MUFU loop)
    #pragma unroll
    for (int it = 0; it < 8; ++it) {
        int e = tid + 512 * it;
        int row = e >> 6;
        int c4  = e & 63;
        float4 v = *reinterpret_cast<const float4*>(Hb + (size_t)(i0 + row) * D + 4 * c4);
        sHi[row * SH2 + 2 * c4]     = __floats2half2_rn(v.x, v.y);
        sHi[row * SH2 + 2 * c4 + 1] = __floats2half2_rn(v.z, v.w);
    }
    #pragma unroll
    for (int it = 0; it < 8; ++it) {
        int e = tid + 512 * it;
        int row = e >> 6;
        int c4  = e & 63;
        float4 v = *reinterpret_cast<const float4*>(Hb + (size_t)(j0 + row) * D + 4 * c4);
        sHj[row * SH2 + 2 * c4]     = __floats2half2_rn(v.x, v.y);
        sHj[row * SH2 + 2 * c4 + 1] = __floats2half2_rn(v.z, v.w);
    }

    // exp tiles: dims [DMU, D), E = exp(2h). 64 rows x 12 float4 = 768 per tile.
    #pragma unroll
    for (int it = 0; it < 2; ++it) {
        int e = tid + 512 * it;
        if (e < 768) {
            int row = e / 12, c4 = e % 12;
            float4 v = *reinterpret_cast<const float4*>(Hb + (size_t)(i0 + row) * D + DMU + 4 * c4);
            float* dst = sEi + row * ELD + 4 * c4;
            dst[0] = __expf(2.0f * v.x); dst[1] = __expf(2.0f * v.y);
            dst[2] = __expf(2.0f * v.z); dst[3] = __expf(2.0f * v.w);
        }
    }
    #pragma unroll
    for (int it = 0; it < 2; ++it) {
        int e = tid + 512 * it;
        if (e < 768) {
            int row = e / 12, c4 = e % 12;
            float4 v = *reinterpret_cast<const float4*>(Hb + (size_t)(j0 + row) * D + DMU + 4 * c4);
            float* dst = sEj + row * ELD + 4 * c4;
            dst[0] = __expf(2.0f * v.x); dst[1] = __expf(2.0f * v.y);
            dst[2] = __expf(2.0f * v.z); dst[3] = __expf(2.0f * v.w);
        }
    }
    __syncthreads();

    const int tx = tid & 15;
    const int ty = tid >> 4;

    float accf[2][4];
    #pragma unroll
    for (int m = 0; m < 2; ++m)
        #pragma unroll
        for (int n = 0; n < 4; ++n) accf[m][n] = 0.0f;

    // ---- Part 1: MUFU f16x2 path, 104 pairs (26 chunks of 4) -------------
    #pragma unroll 2
    for (int c = 0; c < DMU / 8; ++c) {
        __half2 acc2[2][4];
        #pragma unroll
        for (int m = 0; m < 2; ++m)
            #pragma unroll
            for (int n = 0; n < 4; ++n)
                acc2[m][n] = __halves2half2(__ushort_as_half(0), __ushort_as_half(0));

        #pragma unroll
        for (int u = 0; u < 4; ++u) {
            const int dp = 4 * c + u;
            const __half2 w2 = sWh[dp];
            __half2 hi[2], hj[4];
            #pragma unroll
            for (int m = 0; m < 2; ++m) hi[m] = sHi[(ty + 32 * m) * SH2 + dp];
            #pragma unroll
            for (int n = 0; n < 4; ++n) hj[n] = sHj[(tx + 16 * n) * SH2 + dp];
            #pragma unroll
            for (int m = 0; m < 2; ++m)
                #pragma unroll
                for (int n = 0; n < 4; ++n) {
                    __half2 t = tanh2_approx(__hadd2(hi[m], hj[n]));
                    acc2[m][n] = __hfma2(t, w2, acc2[m][n]);
                }
        }

        #pragma unroll
        for (int m = 0; m < 2; ++m)
            #pragma unroll
            for (int n = 0; n < 4; ++n) {
                float2 f = __half22float2(acc2[m][n]);
                accf[m][n] += f.x + f.y;
            }
    }

    // ---- Part 2: exp-identity path, 48 fp32 dims on the FMA/ALU pipes ----
    #pragma unroll 2
    for (int d = 0; d < NID; ++d) {
        const float wd = sWf[d];
        float Ei[2], Ej[4];
        #pragma unroll
        for (int m = 0; m < 2; ++m) Ei[m] = sEi[(ty + 32 * m) * ELD + d];
        #pragma unroll
        for (int n = 0; n < 4; ++n) Ej[n] = sEj[(tx + 16 * n) * ELD + d];
        #pragma unroll
        for (int m = 0; m < 2; ++m)
            #pragma unroll
            for (int n = 0; n < 4; ++n) {
                float P   = Ei[m] * Ej[n];
                float y   = frcp2(P + 1.0f);
                float t   = (P - 1.0f) * y;        // = tanh(hi+hj) exactly
                accf[m][n] = fmaf(t, wd, accf[m][n]);
            }
    }

    const int mirror = (ti != tj);
    #pragma unroll
    for (int m = 0; m < 2; ++m) {
        int gi = i0 + ty + 32 * m;
        #pragma unroll
        for (int n = 0; n < 4; ++n) {
            int gj = j0 + tx + 16 * n;
            float v = accf[m][n];
            g_scores[((size_t)b * L + gi) * L + gj] = v;
            if (mirror)
                g_scores[((size_t)b * L + gj) * L + gi] = v;
        }
    }
}

// ---------------------------------------------------------------------------
// Kernel 2 (round-15 proven): warp-per-row softmax; fp32 alpha to d_out +
// fp16 alpha scratch. Grid: 256 CTAs x 256 thr = 2048 warps = B*L rows.
// ---------------------------------------------------------------------------
__device__ __half g_alpha_h[A_SIZE];

__global__ void __launch_bounds__(256)
softmax_kernel(float* __restrict__ out_alpha) {
    const int lane = threadIdx.x & 31;
    const int row  = blockIdx.x * 8 + (threadIdx.x >> 5);   // 0..2047
    const float4* S4 = reinterpret_cast<const float4*>(g_scores + (size_t)row * L);

    float4 v[4];
    #pragma unroll
    for (int k = 0; k < 4; ++k) v[k] = S4[lane + 32 * k];

    float mx = -1e30f;
    #pragma unroll
    for (int k = 0; k < 4; ++k)
        mx = fmaxf(mx, fmaxf(fmaxf(v[k].x, v[k].y), fmaxf(v[k].z, v[k].w)));
    #pragma unroll
    for (int o = 16; o; o >>= 1) mx = fmaxf(mx, __shfl_xor_sync(0xffffffffu, mx, o));

    float s = 0.0f;
    #pragma unroll
    for (int k = 0; k < 4; ++k) {
        v[k].x = __expf(v[k].x - mx); v[k].y = __expf(v[k].y - mx);
        v[k].z = __expf(v[k].z - mx); v[k].w = __expf(v[k].w - mx);
        s += (v[k].x + v[k].y) + (v[k].z + v[k].w);
    }
    #pragma unroll
    for (int o = 16; o; o >>= 1) s += __shfl_xor_sync(0xffffffffu, s, o);
    const float inv = 1.0f / s;

    float4* A4 = reinterpret_cast<float4*>(out_alpha + (size_t)row * L);
    __half2* Ah2 = reinterpret_cast<__half2*>(g_alpha_h + (size_t)row * L);
    #pragma unroll
    for (int k = 0; k < 4; ++k) {
        float4 o4 = make_float4(v[k].x * inv, v[k].y * inv, v[k].z * inv, v[k].w * inv);
        A4[lane + 32 * k] = o4;
        Ah2[2 * (lane + 32 * k)]     = __floats2half2_rn(o4.x, o4.y);
        Ah2[2 * (lane + 32 * k) + 1] = __floats2half2_rn(o4.z, o4.w);
    }
}

// ---------------------------------------------------------------------------
// Kernel 3 (round-15 proven): r[b] = alpha[b] @ H[b] on the tensor pipe,
// smem-staged. CTA: 64x128; grid (2, 8, 4) = 64 CTAs, 256 thr (8 warps).
// ---------------------------------------------------------------------------
#define ALD 72    // alpha smem row stride (halves)
#define HLD 136   // H smem row stride (halves)
#define ATILE (64 * ALD)
#define HTILE (64 * HLD)

__global__ void __launch_bounds__(256)
gemm_wmma(float* __restrict__ out_r) {
    extern __shared__ __align__(16) __half wsm[];
    __half* As = wsm;              // 2 * ATILE
    __half* Bs = wsm + 2 * ATILE;  // 2 * HTILE

    const int d0  = blockIdx.x * 128;
    const int it0 = blockIdx.y * 64;
    const int b   = blockIdx.z;

    const __half* A  = g_alpha_h + ((size_t)b * L + it0) * L;      // 64 x 512
    const __half* Hm = g_H_h     + (size_t)b * L * D + d0;         // 512 x 128
    float*        C  = out_r     + ((size_t)b * L + it0) * D + d0;

    const int tid  = threadIdx.x;
    const int warp = tid >> 5;
    const int wy   = warp >> 1;    // 0..3: i-subtile (16 rows)
    const int wx   = warp & 1;     // 0..1: d-subtile (64 cols)

    wmma::fragment<wmma::accumulator, 16, 16, 16, float> acc[4];
    #pragma unroll
    for (int n = 0; n < 4; ++n) wmma::fill_fragment(acc[n], 0.0f);

    #pragma unroll
    for (int t = 0; t < 2; ++t) {                 // alpha: 512 float4
        int e = tid + 256 * t;
        int row = e >> 3, c4 = e & 7;
        float4 v = *reinterpret_cast<const float4*>(A + (size_t)row * L + 8 * c4);
        *reinterpret_cast<float4*>(As + row * ALD + 8 * c4) = v;
    }
    #pragma unroll
    for (int t = 0; t < 4; ++t) {                 // H: 1024 float4
        int e = tid + 256 * t;
        int row = e >> 4, c4 = e & 15;
        float4 v = *reinterpret_cast<const float4*>(Hm + (size_t)row * D + 8 * c4);
        *reinterpret_cast<float4*>(Bs + row * HLD + 8 * c4) = v;
    }
    __syncthreads();

    #pragma unroll 1
    for (int kt = 0; kt < 8; ++kt) {
        const int cur = kt & 1, nxt = cur ^ 1;

        float4 pa[2], pb[4];
        if (kt < 7) {
            const int k0n = (kt + 1) * 64;
            #pragma unroll
            for (int t = 0; t < 2; ++t) {
                int e = tid + 256 * t;
                int row = e >> 3, c4 = e & 7;
                pa[t] = *reinterpret_cast<const float4*>(A + (size_t)row * L + k0n + 8 * c4);
            }
            #pragma unroll
            for (int t = 0; t < 4; ++t) {
                int e = tid + 256 * t;
                int row = e >> 4, c4 = e & 15;
                pb[t] = *reinterpret_cast<const float4*>(Hm + (size_t)(k0n + row) * D + 8 * c4);
            }
        }

        const __half* Ac = As + cur * ATILE;
        const __half* Bc = Bs + cur * HTILE;
        #pragma unroll
        for (int ks = 0; ks < 4; ++ks) {
            wmma::fragment<wmma::matrix_a, 16, 16, 16, __half, wmma::row_major> af;
            wmma::load_matrix_sync(af, Ac + (wy * 16) * ALD + ks * 16, ALD);
            #pragma unroll
            for (int n = 0; n < 4; ++n) {
                wmma::fragment<wmma::matrix_b, 16, 16, 16, __half, wmma::row_major> bf;
                wmma::load_matrix_sync(bf, Bc + (ks * 16) * HLD + wx * 64 + n * 16, HLD);
                wmma::mma_sync(acc[n], af, bf, acc[n]);
            }
        }

        if (kt < 7) {
            __half* An = As + nxt * ATILE;
            __half* Bn = Bs + nxt * HTILE;
            #pragma unroll
            for (int t = 0; t < 2; ++t) {
                int e = tid + 256 * t;
                int row = e >> 3, c4 = e & 7;
                *reinterpret_cast<float4*>(An + row * ALD + 8 * c4) = pa[t];
            }
            #pragma unroll
            for (int t = 0; t < 4; ++t) {
                int e = tid + 256 * t;
                int row = e >> 4, c4 = e & 15;
                *reinterpret_cast<float4*>(Bn + row * HLD + 8 * c4) = pb[t];
            }
        }
        __syncthreads();
    }

    #pragma unroll
    for (int n = 0; n < 4; ++n)
        wmma::store_matrix_sync(C + (size_t)(wy * 16) * D + wx * 64 + n * 16,
                                acc[n], D, wmma::mem_row_major);
}

// ---------------------------------------------------------------------------
extern "C" void kernel_launch(void* const* d_in, const int* in_sizes, int n_in,
                              void* d_out, int out_size) {
    const float* H = (const float*)d_in[0];
    const float* w = (const float*)d_in[1];

    float* out   = (float*)d_out;
    float* r     = out;            // first R_SIZE floats
    float* alpha = out + R_SIZE;   // next A_SIZE floats

    const int smem1 = (2 * 64 * SH2 + D2) * (int)sizeof(__half2)
                    + (2 * 64 * ELD + NID) * (int)sizeof(float);
    cudaFuncSetAttribute(scores_kernel,
                         cudaFuncAttributeMaxDynamicSharedMemorySize, smem1);

    const int smem3 = (2 * ATILE + 2 * HTILE) * (int)sizeof(__half);
    cudaFuncSetAttribute(gemm_wmma,
                         cudaFuncAttributeMaxDynamicSharedMemorySize, smem3);

    scores_kernel<<<SCORES_GRID, 512, smem1>>>(H, w);
    softmax_kernel<<<256, 256>>>(alpha);
    gemm_wmma<<<dim3(2, 8, 4), 256, smem3>>>(r);
}